// round 2
// baseline (speedup 1.0000x reference)
#include <cuda_runtime.h>
#include <math.h>

#define Bn 4
#define Tn 8
#define Hn 256
#define Wn 256
#define NPIX (Bn*Tn*Hn*Wn)   // 2,097,152 elements per field

typedef unsigned long long u64;

// Scratch (static device globals -- no allocation allowed)
// fields: 0:kappa^2 1:m1 2:m2 3:Hxx 4:(Hxy+Hyx) 5:unused 6:Hyy 7:D
__device__ float g_fields[8][NPIX];
__device__ float g_v[NPIX];          // v = A(x)
__device__ double g_acc[2];          // [0] = sum(D r^2), [1] = sum(log D)

__global__ void init_acc_kernel() {
    g_acc[0] = 0.0;
    g_acc[1] = 0.0;
}

// ---------------------------------------------------------------------------
// packed f32x2 helpers (Blackwell)
// ---------------------------------------------------------------------------
__device__ __forceinline__ u64 fma2(u64 a, u64 b, u64 c) {
    u64 d;
    asm("fma.rn.f32x2 %0, %1, %2, %3;" : "=l"(d) : "l"(a), "l"(b), "l"(c));
    return d;
}
__device__ __forceinline__ u64 dup2(float x) {
    u64 d;
    unsigned int xi = __float_as_uint(x);
    asm("mov.b64 %0, {%1, %1};" : "=l"(d) : "r"(xi));
    return d;
}
__device__ __forceinline__ void unpack2(u64 v, float& lo, float& hi) {
    unsigned int a, b;
    asm("mov.b64 {%0, %1}, %2;" : "=r"(a), "=r"(b) : "l"(v));
    lo = __uint_as_float(a);
    hi = __uint_as_float(b);
}

// ---------------------------------------------------------------------------
// Kernel 1: 3x3 conv (8 -> 64 channels) via f32x2 packed FMA,
// per-group nonlinearity, Hxy+Hyx merged through smem, field store.
// Tile: 32 wide x 8 tall pixels. 256 threads. warp id (tn) = output group g.
// ---------------------------------------------------------------------------
#define TW 32
#define TH 8

__global__ __launch_bounds__(256) void conv_kernel(const float* __restrict__ x,
                                                   const float* __restrict__ cw)
{
    __shared__ float xs[8][TH + 2][TW + 2];        // 8 ch x 10 x 34
    __shared__ __align__(16) float ws[72 * 64];    // [k][o], o fastest
    __shared__ float hy[8][8][32];                 // warp5's 0.1*tanh values

    const int tid = threadIdx.x;
    const int b  = blockIdx.z;
    const int h0 = blockIdx.y * TH;
    const int w0 = blockIdx.x * TW;

    // weights transposed: ws[k*64 + o] = cw[o*72 + k]
    for (int i = tid; i < 72 * 64; i += 256) {
        int k = i >> 6, o = i & 63;
        ws[i] = cw[o * 72 + k];
    }
    // x tile with halo 1 (zero Dirichlet)
    for (int i = tid; i < 8 * (TH + 2) * (TW + 2); i += 256) {
        int ci  = i / ((TH + 2) * (TW + 2));
        int rem = i % ((TH + 2) * (TW + 2));
        int yy  = rem / (TW + 2);
        int xx  = rem % (TW + 2);
        int gy = h0 - 1 + yy, gx = w0 - 1 + xx;
        float v = 0.f;
        if (gy >= 0 && gy < Hn && gx >= 0 && gx < Wn)
            v = x[(((b * Tn) + ci) * Hn + gy) * Wn + gx];
        xs[ci][yy][xx] = v;
    }
    __syncthreads();

    const int tn = tid >> 5;   // warp = group g (0..7)
    const int tm = tid & 31;   // pixel column within tile

    // acc2[i][j2]: row i, channel pair (2*j2, 2*j2+1) within group
    u64 acc2[8][4];
    #pragma unroll
    for (int i = 0; i < 8; i++)
        #pragma unroll
        for (int j = 0; j < 4; j++) acc2[i][j] = 0ull;

    const int obase = tn * 8;
    for (int ci = 0; ci < 8; ci++) {
        #pragma unroll
        for (int ky = 0; ky < 3; ky++) {
            #pragma unroll
            for (int kx = 0; kx < 3; kx++) {
                const int k = ci * 9 + ky * 3 + kx;
                const ulonglong2* wp = (const ulonglong2*)&ws[k * 64 + obase];
                ulonglong2 wa = wp[0];   // (w0,w1) (w2,w3)
                ulonglong2 wb = wp[1];   // (w4,w5) (w6,w7)
                #pragma unroll
                for (int i = 0; i < 8; i++) {
                    u64 xd = dup2(xs[ci][i + ky][tm + kx]);
                    acc2[i][0] = fma2(xd, wa.x, acc2[i][0]);
                    acc2[i][1] = fma2(xd, wa.y, acc2[i][1]);
                    acc2[i][2] = fma2(xd, wb.x, acc2[i][2]);
                    acc2[i][3] = fma2(xd, wb.y, acc2[i][3]);
                }
            }
        }
    }

    // warp 5 (Hyx): deposit 0.1*tanh into smem for warp 4 to merge
    if (tn == 5) {
        #pragma unroll
        for (int i = 0; i < 8; i++) {
            #pragma unroll
            for (int j2 = 0; j2 < 4; j2++) {
                float t0, t1;
                unpack2(acc2[i][j2], t0, t1);
                hy[i][2 * j2][tm]     = 0.1f * tanhf(t0);
                hy[i][2 * j2 + 1][tm] = 0.1f * tanhf(t1);
            }
        }
    }
    __syncthreads();

    float lsum = 0.f;
    if (tn != 5) {
        #pragma unroll
        for (int i = 0; i < 8; i++) {
            const int h = h0 + i;
            #pragma unroll
            for (int j2 = 0; j2 < 4; j2++) {
                float t0, t1;
                unpack2(acc2[i][j2], t0, t1);
                float r0, r1;
                if (tn == 0) {                       // kappa -> kappa^2
                    float s0 = 1.f / (1.f + expf(-t0));
                    float s1 = 1.f / (1.f + expf(-t1));
                    float k0 = s0 * 0.99f + 0.01f;
                    float k1 = s1 * 0.99f + 0.01f;
                    r0 = k0 * k0; r1 = k1 * k1;
                } else if (tn == 1 || tn == 2) {     // m1, m2 raw
                    r0 = t0; r1 = t1;
                } else if (tn == 3 || tn == 6) {     // Hxx, Hyy
                    r0 = (1.f / (1.f + expf(-t0))) * 0.99f + 0.01f;
                    r1 = (1.f / (1.f + expf(-t1))) * 0.99f + 0.01f;
                } else if (tn == 4) {                // Hxy + Hyx (merged)
                    r0 = 0.1f * tanhf(t0) + hy[i][2 * j2][tm];
                    r1 = 0.1f * tanhf(t1) + hy[i][2 * j2 + 1][tm];
                } else {                             // tau -> D = 1/tau^2
                    float s0 = 1.f / (1.f + expf(-t0));
                    float s1 = 1.f / (1.f + expf(-t1));
                    float ta0 = s0 * 9.9f + 0.1f;
                    float ta1 = s1 * 9.9f + 0.1f;
                    r0 = 1.f / (ta0 * ta0);
                    r1 = 1.f / (ta1 * ta1);
                    lsum += logf(r0) + logf(r1);
                }
                const int j0 = 2 * j2;
                g_fields[tn][(((b * Tn) + j0)     * Hn + h) * Wn + w0 + tm] = r0;
                g_fields[tn][(((b * Tn) + j0 + 1) * Hn + h) * Wn + w0 + tm] = r1;
            }
        }
    }

    if (tn == 7) {   // accumulate logdet(D)
        #pragma unroll
        for (int off = 16; off; off >>= 1)
            lsum += __shfl_down_sync(0xffffffffu, lsum, off);
        if (tm == 0) atomicAdd(&g_acc[1], (double)lsum);
    }
}

// ---------------------------------------------------------------------------
// Vectorized stencil: operator A on 4 consecutive pixels.
// ---------------------------------------------------------------------------
__device__ __forceinline__ void loadrow6(const float* __restrict__ row, int w4,
                                         float* arr)
{
    float4 v = *(const float4*)(row + w4);
    arr[0] = (w4 > 0)      ? row[w4 - 1] : 0.f;
    arr[1] = v.x; arr[2] = v.y; arr[3] = v.z; arr[4] = v.w;
    arr[5] = (w4 + 4 < Wn) ? row[w4 + 4] : 0.f;
}

__device__ __forceinline__ float4 applyA4(const float* __restrict__ u,
                                          int base, int h, int w4)
{
    float cc[6], uu[6], dd[6];
    const float* row = u + base + h * Wn;
    loadrow6(row, w4, cc);
    if (h > 0)       loadrow6(row - Wn, w4, uu);
    else { uu[0]=uu[1]=uu[2]=uu[3]=uu[4]=uu[5]=0.f; }
    if (h + 1 < Hn)  loadrow6(row + Wn, w4, dd);
    else { dd[0]=dd[1]=dd[2]=dd[3]=dd[4]=dd[5]=0.f; }

    const int p = base + h * Wn + w4;
    float4 q0 = *(const float4*)&g_fields[0][p];
    float4 q1 = *(const float4*)&g_fields[1][p];
    float4 q2 = *(const float4*)&g_fields[2][p];
    float4 q3 = *(const float4*)&g_fields[3][p];
    float4 q4 = *(const float4*)&g_fields[4][p];
    float4 q6 = *(const float4*)&g_fields[6][p];
    float f0a[4] = {q0.x, q0.y, q0.z, q0.w};
    float f1a[4] = {q1.x, q1.y, q1.z, q1.w};
    float f2a[4] = {q2.x, q2.y, q2.z, q2.w};
    float f3a[4] = {q3.x, q3.y, q3.z, q3.w};
    float f4a[4] = {q4.x, q4.y, q4.z, q4.w};
    float f6a[4] = {q6.x, q6.y, q6.z, q6.w};

    float out[4];
    #pragma unroll
    for (int j = 0; j < 4; j++) {
        float c   = cc[j + 1];
        float dx  = 0.5f  * (cc[j + 2] - cc[j]);
        float dy  = 0.5f  * (dd[j + 1] - uu[j + 1]);
        float dxx = cc[j + 2] + cc[j] - 2.f * c;
        float dyy = dd[j + 1] + uu[j + 1] - 2.f * c;
        float dxy = 0.25f * ((dd[j + 2] - uu[j + 2]) - (dd[j] - uu[j]));
        out[j] = f0a[j] * c + f1a[j] * dx + f2a[j] * dy
               - (f3a[j] * dxx + f6a[j] * dyy + f4a[j] * dxy);
    }
    return make_float4(out[0], out[1], out[2], out[3]);
}

// Kernel 2: v = A(x)   -- 256 threads, 4 rows x 64 float4-lanes per block
__global__ __launch_bounds__(256) void stencil1_kernel(const float* __restrict__ x)
{
    const int tx = threadIdx.x & 63;
    const int ty = threadIdx.x >> 6;
    const int h  = blockIdx.x * 4 + ty;
    const int t  = blockIdx.y;
    const int b  = blockIdx.z;
    const int base = ((b * Tn + t) * Hn) * Wn;
    const int w4 = tx * 4;
    float4 r = applyA4(x, base, h, w4);
    *(float4*)&g_v[base + h * Wn + w4] = r;
}

// Kernel 3: r = x + A(v) - x_prev ; accumulate sum(D r^2)
__global__ __launch_bounds__(256) void stencil2_kernel(const float* __restrict__ x)
{
    const int tx = threadIdx.x & 63;
    const int ty = threadIdx.x >> 6;
    const int h  = blockIdx.x * 4 + ty;
    const int t  = blockIdx.y;
    const int b  = blockIdx.z;
    const int base = ((b * Tn + t) * Hn) * Wn;
    const int w4 = tx * 4;
    const int p  = base + h * Wn + w4;

    float4 Av = applyA4(g_v, base, h, w4);
    float4 xv = *(const float4*)&x[p];
    float4 xp = make_float4(0.f, 0.f, 0.f, 0.f);
    if (t > 0) xp = *(const float4*)&x[p - Hn * Wn];
    float4 f7 = *(const float4*)&g_fields[7][p];

    float r0 = xv.x + Av.x - xp.x;
    float r1 = xv.y + Av.y - xp.y;
    float r2 = xv.z + Av.z - xp.z;
    float r3 = xv.w + Av.w - xp.w;
    float val = f7.x * r0 * r0 + f7.y * r1 * r1 + f7.z * r2 * r2 + f7.w * r3 * r3;

    #pragma unroll
    for (int off = 16; off; off >>= 1)
        val += __shfl_down_sync(0xffffffffu, val, off);

    __shared__ float red[8];
    const int lane = threadIdx.x & 31;
    const int wid  = threadIdx.x >> 5;
    if (lane == 0) red[wid] = val;
    __syncthreads();
    if (wid == 0) {
        float s = (lane < 8) ? red[lane] : 0.f;
        #pragma unroll
        for (int off = 4; off; off >>= 1)
            s += __shfl_down_sync(0xffffffffu, s, off);
        if (lane == 0) atomicAdd(&g_acc[0], (double)s);
    }
}

__global__ void finalize_kernel(float* __restrict__ out)
{
    out[0] = (float)(0.5 * (g_acc[0] - g_acc[1]));
}

// ---------------------------------------------------------------------------
extern "C" void kernel_launch(void* const* d_in, const int* in_sizes, int n_in,
                              void* d_out, int out_size)
{
    const float* x  = (const float*)d_in[0];
    const float* cw = (const float*)d_in[1];
    float* out = (float*)d_out;

    init_acc_kernel<<<1, 1>>>();

    dim3 gA(Wn / TW, Hn / TH, Bn);       // 8 x 32 x 4 = 1024 blocks
    conv_kernel<<<gA, 256>>>(x, cw);

    dim3 gS(Hn / 4, Tn, Bn);             // 64 x 8 x 4 = 2048 blocks, 256 thr
    stencil1_kernel<<<gS, 256>>>(x);
    stencil2_kernel<<<gS, 256>>>(x);

    finalize_kernel<<<1, 1>>>(out);
}

// round 3
// speedup vs baseline: 1.1652x; 1.1652x over previous
#include <cuda_runtime.h>
#include <math.h>

#define Bn 4
#define Tn 8
#define Hn 256
#define Wn 256
#define NPIX (Bn*Tn*Hn*Wn)   // 2,097,152 elements per field

// Scratch (static device globals -- no allocation allowed)
// fields: 0:kappa^2 1:m1 2:m2 3:Hxx 4:(Hxy+Hyx) 5:unused 6:Hyy 7:D
__device__ float g_fields[8][NPIX];
__device__ float g_v[NPIX];          // v = A(x)
__device__ double g_acc[2];          // [0] = sum(D r^2), [1] = sum(log D)

__global__ void init_acc_kernel() {
    g_acc[0] = 0.0;
    g_acc[1] = 0.0;
}

// ---------------------------------------------------------------------------
// Kernel 1: 3x3 conv (8 -> 64 channels), scalar FFMA, low register pressure.
// Tile: 32 wide x 4 tall. 256 threads, warp id = output group g (8 channels).
// Each thread: 4 rows x 8 channels = 32 accumulators.
// ---------------------------------------------------------------------------
#define TW 32
#define TH 4

__global__ __launch_bounds__(256, 4) void conv_kernel(const float* __restrict__ x,
                                                      const float* __restrict__ cw)
{
    __shared__ float xs[8][TH + 2][TW + 2];        // 8 ch x 6 x 34  (6.5KB)
    __shared__ __align__(16) float ws[72 * 64];    // [k][o], o fastest (18KB)
    __shared__ float hy[TH][8][32];                // warp5's 0.1*tanh (4KB)

    const int tid = threadIdx.x;
    const int b  = blockIdx.z;
    const int h0 = blockIdx.y * TH;
    const int w0 = blockIdx.x * TW;

    // weights transposed: ws[k*64 + o] = cw[o*72 + k]
    for (int i = tid; i < 72 * 64; i += 256) {
        int k = i >> 6, o = i & 63;
        ws[i] = cw[o * 72 + k];
    }
    // x tile with halo 1 (zero Dirichlet)
    for (int i = tid; i < 8 * (TH + 2) * (TW + 2); i += 256) {
        int ci  = i / ((TH + 2) * (TW + 2));
        int rem = i % ((TH + 2) * (TW + 2));
        int yy  = rem / (TW + 2);
        int xx  = rem % (TW + 2);
        int gy = h0 - 1 + yy, gx = w0 - 1 + xx;
        float v = 0.f;
        if (gy >= 0 && gy < Hn && gx >= 0 && gx < Wn)
            v = x[(((b * Tn) + ci) * Hn + gy) * Wn + gx];
        xs[ci][yy][xx] = v;
    }
    __syncthreads();

    const int tn = tid >> 5;   // warp = group g (0..7)
    const int tm = tid & 31;   // pixel column within tile

    float acc[TH][8];
    #pragma unroll
    for (int i = 0; i < TH; i++)
        #pragma unroll
        for (int j = 0; j < 8; j++) acc[i][j] = 0.f;

    const int obase = tn * 8;
    for (int ci = 0; ci < 8; ci++) {
        #pragma unroll
        for (int ky = 0; ky < 3; ky++) {
            #pragma unroll
            for (int kx = 0; kx < 3; kx++) {
                const int k = ci * 9 + ky * 3 + kx;
                float4 wv0 = *(const float4*)&ws[k * 64 + obase];
                float4 wv1 = *(const float4*)&ws[k * 64 + obase + 4];
                #pragma unroll
                for (int i = 0; i < TH; i++) {
                    float xv = xs[ci][i + ky][tm + kx];
                    acc[i][0] += xv * wv0.x;
                    acc[i][1] += xv * wv0.y;
                    acc[i][2] += xv * wv0.z;
                    acc[i][3] += xv * wv0.w;
                    acc[i][4] += xv * wv1.x;
                    acc[i][5] += xv * wv1.y;
                    acc[i][6] += xv * wv1.z;
                    acc[i][7] += xv * wv1.w;
                }
            }
        }
    }

    // warp 5 (Hyx): deposit 0.1*tanh into smem for warp 4 to merge
    if (tn == 5) {
        #pragma unroll
        for (int i = 0; i < TH; i++)
            #pragma unroll
            for (int j = 0; j < 8; j++)
                hy[i][j][tm] = 0.1f * tanhf(acc[i][j]);
    }
    __syncthreads();

    float lsum = 0.f;
    if (tn != 5) {
        #pragma unroll
        for (int i = 0; i < TH; i++) {
            const int h = h0 + i;
            #pragma unroll
            for (int j = 0; j < 8; j++) {
                float a = acc[i][j];
                float r;
                if (tn == 0) {                       // kappa -> kappa^2
                    float s = 1.f / (1.f + expf(-a));
                    float kp = s * 0.99f + 0.01f;
                    r = kp * kp;
                } else if (tn == 1 || tn == 2) {     // m1, m2 raw
                    r = a;
                } else if (tn == 3 || tn == 6) {     // Hxx, Hyy
                    r = (1.f / (1.f + expf(-a))) * 0.99f + 0.01f;
                } else if (tn == 4) {                // Hxy + Hyx (merged)
                    r = 0.1f * tanhf(a) + hy[i][j][tm];
                } else {                             // tau -> D = 1/tau^2
                    float s = 1.f / (1.f + expf(-a));
                    float tau = s * 9.9f + 0.1f;
                    r = 1.f / (tau * tau);
                    lsum += logf(r);
                }
                g_fields[tn][(((b * Tn) + j) * Hn + h) * Wn + w0 + tm] = r;
            }
        }
    }

    if (tn == 7) {   // accumulate logdet(D)
        #pragma unroll
        for (int off = 16; off; off >>= 1)
            lsum += __shfl_down_sync(0xffffffffu, lsum, off);
        if (tm == 0) atomicAdd(&g_acc[1], (double)lsum);
    }
}

// ---------------------------------------------------------------------------
// Vectorized stencil: operator A on 4 consecutive pixels.
// ---------------------------------------------------------------------------
__device__ __forceinline__ void loadrow6(const float* __restrict__ row, int w4,
                                         float* arr)
{
    float4 v = *(const float4*)(row + w4);
    arr[0] = (w4 > 0)      ? row[w4 - 1] : 0.f;
    arr[1] = v.x; arr[2] = v.y; arr[3] = v.z; arr[4] = v.w;
    arr[5] = (w4 + 4 < Wn) ? row[w4 + 4] : 0.f;
}

__device__ __forceinline__ float4 applyA4(const float* __restrict__ u,
                                          int base, int h, int w4)
{
    float cc[6], uu[6], dd[6];
    const float* row = u + base + h * Wn;
    loadrow6(row, w4, cc);
    if (h > 0)       loadrow6(row - Wn, w4, uu);
    else { uu[0]=uu[1]=uu[2]=uu[3]=uu[4]=uu[5]=0.f; }
    if (h + 1 < Hn)  loadrow6(row + Wn, w4, dd);
    else { dd[0]=dd[1]=dd[2]=dd[3]=dd[4]=dd[5]=0.f; }

    const int p = base + h * Wn + w4;
    float4 q0 = *(const float4*)&g_fields[0][p];
    float4 q1 = *(const float4*)&g_fields[1][p];
    float4 q2 = *(const float4*)&g_fields[2][p];
    float4 q3 = *(const float4*)&g_fields[3][p];
    float4 q4 = *(const float4*)&g_fields[4][p];
    float4 q6 = *(const float4*)&g_fields[6][p];
    float f0a[4] = {q0.x, q0.y, q0.z, q0.w};
    float f1a[4] = {q1.x, q1.y, q1.z, q1.w};
    float f2a[4] = {q2.x, q2.y, q2.z, q2.w};
    float f3a[4] = {q3.x, q3.y, q3.z, q3.w};
    float f4a[4] = {q4.x, q4.y, q4.z, q4.w};
    float f6a[4] = {q6.x, q6.y, q6.z, q6.w};

    float out[4];
    #pragma unroll
    for (int j = 0; j < 4; j++) {
        float c   = cc[j + 1];
        float dx  = 0.5f  * (cc[j + 2] - cc[j]);
        float dy  = 0.5f  * (dd[j + 1] - uu[j + 1]);
        float dxx = cc[j + 2] + cc[j] - 2.f * c;
        float dyy = dd[j + 1] + uu[j + 1] - 2.f * c;
        float dxy = 0.25f * ((dd[j + 2] - uu[j + 2]) - (dd[j] - uu[j]));
        out[j] = f0a[j] * c + f1a[j] * dx + f2a[j] * dy
               - (f3a[j] * dxx + f6a[j] * dyy + f4a[j] * dxy);
    }
    return make_float4(out[0], out[1], out[2], out[3]);
}

// Kernel 2: v = A(x)   -- 256 threads, 4 rows x 64 float4-lanes per block
__global__ __launch_bounds__(256) void stencil1_kernel(const float* __restrict__ x)
{
    const int tx = threadIdx.x & 63;
    const int ty = threadIdx.x >> 6;
    const int h  = blockIdx.x * 4 + ty;
    const int t  = blockIdx.y;
    const int b  = blockIdx.z;
    const int base = ((b * Tn + t) * Hn) * Wn;
    const int w4 = tx * 4;
    float4 r = applyA4(x, base, h, w4);
    *(float4*)&g_v[base + h * Wn + w4] = r;
}

// Kernel 3: r = x + A(v) - x_prev ; accumulate sum(D r^2)
__global__ __launch_bounds__(256) void stencil2_kernel(const float* __restrict__ x)
{
    const int tx = threadIdx.x & 63;
    const int ty = threadIdx.x >> 6;
    const int h  = blockIdx.x * 4 + ty;
    const int t  = blockIdx.y;
    const int b  = blockIdx.z;
    const int base = ((b * Tn + t) * Hn) * Wn;
    const int w4 = tx * 4;
    const int p  = base + h * Wn + w4;

    float4 Av = applyA4(g_v, base, h, w4);
    float4 xv = *(const float4*)&x[p];
    float4 xp = make_float4(0.f, 0.f, 0.f, 0.f);
    if (t > 0) xp = *(const float4*)&x[p - Hn * Wn];
    float4 f7 = *(const float4*)&g_fields[7][p];

    float r0 = xv.x + Av.x - xp.x;
    float r1 = xv.y + Av.y - xp.y;
    float r2 = xv.z + Av.z - xp.z;
    float r3 = xv.w + Av.w - xp.w;
    float val = f7.x * r0 * r0 + f7.y * r1 * r1 + f7.z * r2 * r2 + f7.w * r3 * r3;

    #pragma unroll
    for (int off = 16; off; off >>= 1)
        val += __shfl_down_sync(0xffffffffu, val, off);

    __shared__ float red[8];
    const int lane = threadIdx.x & 31;
    const int wid  = threadIdx.x >> 5;
    if (lane == 0) red[wid] = val;
    __syncthreads();
    if (wid == 0) {
        float s = (lane < 8) ? red[lane] : 0.f;
        #pragma unroll
        for (int off = 4; off; off >>= 1)
            s += __shfl_down_sync(0xffffffffu, s, off);
        if (lane == 0) atomicAdd(&g_acc[0], (double)s);
    }
}

__global__ void finalize_kernel(float* __restrict__ out)
{
    out[0] = (float)(0.5 * (g_acc[0] - g_acc[1]));
}

// ---------------------------------------------------------------------------
extern "C" void kernel_launch(void* const* d_in, const int* in_sizes, int n_in,
                              void* d_out, int out_size)
{
    const float* x  = (const float*)d_in[0];
    const float* cw = (const float*)d_in[1];
    float* out = (float*)d_out;

    init_acc_kernel<<<1, 1>>>();

    dim3 gA(Wn / TW, Hn / TH, Bn);       // 8 x 64 x 4 = 2048 blocks
    conv_kernel<<<gA, 256>>>(x, cw);

    dim3 gS(Hn / 4, Tn, Bn);             // 64 x 8 x 4 = 2048 blocks, 256 thr
    stencil1_kernel<<<gS, 256>>>(x);
    stencil2_kernel<<<gS, 256>>>(x);

    finalize_kernel<<<1, 1>>>(out);
}

// round 4
// speedup vs baseline: 1.4383x; 1.2344x over previous
#include <cuda_runtime.h>
#include <math.h>

#define Bn 4
#define Tn 8
#define Hn 256
#define Wn 256
#define NPIX (Bn*Tn*Hn*Wn)   // 2,097,152 elements per field

typedef unsigned long long u64;

// Scratch (static device globals -- no allocation allowed)
// fields: 0:kappa^2 1:m1 2:m2 3:Hxx 4:(Hxy+Hyx) 5:unused 6:Hyy 7:D
__device__ float g_fields[8][NPIX];
__device__ float g_v[NPIX];                     // v = A(x)
__device__ __align__(16) float g_ws[72 * 64];   // transposed weights [k][o]
__device__ double g_acc[2];                     // [0]=sum(D r^2) [1]=sum(log D)

__global__ void init_acc_kernel() {
    g_acc[0] = 0.0;
    g_acc[1] = 0.0;
}

// One-off: transpose cw[o][k] (o-major, 64x72) -> g_ws[k][o] (k-major, 72x64).
// Coalesced read; scattered write (cheap, 18KB total).
__global__ __launch_bounds__(256) void transpose_w_kernel(const float* __restrict__ cw)
{
    int i = blockIdx.x * 256 + threadIdx.x;
    if (i < 72 * 64) {
        int o = i / 72, k = i % 72;
        g_ws[k * 64 + o] = cw[i];
    }
}

// ---------------------------------------------------------------------------
// packed f32x2 helpers (Blackwell)
// ---------------------------------------------------------------------------
__device__ __forceinline__ u64 fma2(u64 a, u64 b, u64 c) {
    u64 d;
    asm("fma.rn.f32x2 %0, %1, %2, %3;" : "=l"(d) : "l"(a), "l"(b), "l"(c));
    return d;
}
__device__ __forceinline__ u64 dup2(float x) {
    u64 d;
    unsigned int xi = __float_as_uint(x);
    asm("mov.b64 %0, {%1, %1};" : "=l"(d) : "r"(xi));
    return d;
}
__device__ __forceinline__ void unpack2(u64 v, float& lo, float& hi) {
    unsigned int a, b;
    asm("mov.b64 {%0, %1}, %2;" : "=r"(a), "=r"(b) : "l"(v));
    lo = __uint_as_float(a);
    hi = __uint_as_float(b);
}

// ---------------------------------------------------------------------------
// Kernel 1: 3x3 conv (8 -> 64 channels), f32x2 packed FMA, coalesced weights.
// Tile: 32 wide x 4 tall. 256 threads, warp id = output group g (8 channels).
// Each thread: 4 rows x 4 channel-pairs = 16 u64 accumulators.
// ---------------------------------------------------------------------------
#define TW 32
#define TH 4

__global__ __launch_bounds__(256, 3) void conv_kernel(const float* __restrict__ x)
{
    __shared__ float xs[8][TH + 2][TW + 2];        // 8 ch x 6 x 34  (6.5KB)
    __shared__ __align__(16) float ws[72 * 64];    // [k][o], o fastest (18KB)
    __shared__ float hy[TH][8][32];                // warp5's 0.1*tanh (4KB)

    const int tid = threadIdx.x;
    const int b  = blockIdx.z;
    const int h0 = blockIdx.y * TH;
    const int w0 = blockIdx.x * TW;

    // coalesced copy of pre-transposed weights (float4)
    {
        const float4* src = (const float4*)g_ws;
        float4* dst = (float4*)ws;
        #pragma unroll
        for (int i = tid; i < 72 * 16; i += 256)
            dst[i] = src[i];
    }
    // x tile with halo 1 (zero Dirichlet)
    for (int i = tid; i < 8 * (TH + 2) * (TW + 2); i += 256) {
        int ci  = i / ((TH + 2) * (TW + 2));
        int rem = i % ((TH + 2) * (TW + 2));
        int yy  = rem / (TW + 2);
        int xx  = rem % (TW + 2);
        int gy = h0 - 1 + yy, gx = w0 - 1 + xx;
        float v = 0.f;
        if (gy >= 0 && gy < Hn && gx >= 0 && gx < Wn)
            v = x[(((b * Tn) + ci) * Hn + gy) * Wn + gx];
        xs[ci][yy][xx] = v;
    }
    __syncthreads();

    const int tn = tid >> 5;   // warp = group g (0..7)
    const int tm = tid & 31;   // pixel column within tile

    u64 acc2[TH][4];
    #pragma unroll
    for (int i = 0; i < TH; i++)
        #pragma unroll
        for (int j = 0; j < 4; j++) acc2[i][j] = 0ull;

    const int obase = tn * 8;
    for (int ci = 0; ci < 8; ci++) {
        #pragma unroll
        for (int ky = 0; ky < 3; ky++) {
            #pragma unroll
            for (int kx = 0; kx < 3; kx++) {
                const int k = ci * 9 + ky * 3 + kx;
                const ulonglong2* wp = (const ulonglong2*)&ws[k * 64 + obase];
                ulonglong2 wa = wp[0];   // pairs (0,1) (2,3)
                ulonglong2 wb = wp[1];   // pairs (4,5) (6,7)
                #pragma unroll
                for (int i = 0; i < TH; i++) {
                    u64 xd = dup2(xs[ci][i + ky][tm + kx]);
                    acc2[i][0] = fma2(xd, wa.x, acc2[i][0]);
                    acc2[i][1] = fma2(xd, wa.y, acc2[i][1]);
                    acc2[i][2] = fma2(xd, wb.x, acc2[i][2]);
                    acc2[i][3] = fma2(xd, wb.y, acc2[i][3]);
                }
            }
        }
    }

    // warp 5 (Hyx): deposit 0.1*tanh into smem for warp 4 to merge
    if (tn == 5) {
        #pragma unroll
        for (int i = 0; i < TH; i++) {
            #pragma unroll
            for (int j2 = 0; j2 < 4; j2++) {
                float t0, t1;
                unpack2(acc2[i][j2], t0, t1);
                hy[i][2 * j2][tm]     = 0.1f * tanhf(t0);
                hy[i][2 * j2 + 1][tm] = 0.1f * tanhf(t1);
            }
        }
    }
    __syncthreads();

    float lsum = 0.f;
    if (tn != 5) {
        #pragma unroll
        for (int i = 0; i < TH; i++) {
            const int h = h0 + i;
            #pragma unroll
            for (int j2 = 0; j2 < 4; j2++) {
                float t0, t1;
                unpack2(acc2[i][j2], t0, t1);
                float r0, r1;
                if (tn == 0) {                       // kappa -> kappa^2
                    float s0 = 1.f / (1.f + expf(-t0));
                    float s1 = 1.f / (1.f + expf(-t1));
                    float k0 = s0 * 0.99f + 0.01f;
                    float k1 = s1 * 0.99f + 0.01f;
                    r0 = k0 * k0; r1 = k1 * k1;
                } else if (tn == 1 || tn == 2) {     // m1, m2 raw
                    r0 = t0; r1 = t1;
                } else if (tn == 3 || tn == 6) {     // Hxx, Hyy
                    r0 = (1.f / (1.f + expf(-t0))) * 0.99f + 0.01f;
                    r1 = (1.f / (1.f + expf(-t1))) * 0.99f + 0.01f;
                } else if (tn == 4) {                // Hxy + Hyx (merged)
                    r0 = 0.1f * tanhf(t0) + hy[i][2 * j2][tm];
                    r1 = 0.1f * tanhf(t1) + hy[i][2 * j2 + 1][tm];
                } else {                             // tau -> D = 1/tau^2
                    float s0 = 1.f / (1.f + expf(-t0));
                    float s1 = 1.f / (1.f + expf(-t1));
                    float ta0 = s0 * 9.9f + 0.1f;
                    float ta1 = s1 * 9.9f + 0.1f;
                    r0 = 1.f / (ta0 * ta0);
                    r1 = 1.f / (ta1 * ta1);
                    lsum += logf(r0) + logf(r1);
                }
                const int j0 = 2 * j2;
                g_fields[tn][(((b * Tn) + j0)     * Hn + h) * Wn + w0 + tm] = r0;
                g_fields[tn][(((b * Tn) + j0 + 1) * Hn + h) * Wn + w0 + tm] = r1;
            }
        }
    }

    if (tn == 7) {   // accumulate logdet(D)
        #pragma unroll
        for (int off = 16; off; off >>= 1)
            lsum += __shfl_down_sync(0xffffffffu, lsum, off);
        if (tm == 0) atomicAdd(&g_acc[1], (double)lsum);
    }
}

// ---------------------------------------------------------------------------
// Vectorized stencil: operator A on 4 consecutive pixels.
// ---------------------------------------------------------------------------
__device__ __forceinline__ void loadrow6(const float* __restrict__ row, int w4,
                                         float* arr)
{
    float4 v = *(const float4*)(row + w4);
    arr[0] = (w4 > 0)      ? row[w4 - 1] : 0.f;
    arr[1] = v.x; arr[2] = v.y; arr[3] = v.z; arr[4] = v.w;
    arr[5] = (w4 + 4 < Wn) ? row[w4 + 4] : 0.f;
}

__device__ __forceinline__ float4 applyA4(const float* __restrict__ u,
                                          int base, int h, int w4)
{
    float cc[6], uu[6], dd[6];
    const float* row = u + base + h * Wn;
    loadrow6(row, w4, cc);
    if (h > 0)       loadrow6(row - Wn, w4, uu);
    else { uu[0]=uu[1]=uu[2]=uu[3]=uu[4]=uu[5]=0.f; }
    if (h + 1 < Hn)  loadrow6(row + Wn, w4, dd);
    else { dd[0]=dd[1]=dd[2]=dd[3]=dd[4]=dd[5]=0.f; }

    const int p = base + h * Wn + w4;
    float4 q0 = *(const float4*)&g_fields[0][p];
    float4 q1 = *(const float4*)&g_fields[1][p];
    float4 q2 = *(const float4*)&g_fields[2][p];
    float4 q3 = *(const float4*)&g_fields[3][p];
    float4 q4 = *(const float4*)&g_fields[4][p];
    float4 q6 = *(const float4*)&g_fields[6][p];
    float f0a[4] = {q0.x, q0.y, q0.z, q0.w};
    float f1a[4] = {q1.x, q1.y, q1.z, q1.w};
    float f2a[4] = {q2.x, q2.y, q2.z, q2.w};
    float f3a[4] = {q3.x, q3.y, q3.z, q3.w};
    float f4a[4] = {q4.x, q4.y, q4.z, q4.w};
    float f6a[4] = {q6.x, q6.y, q6.z, q6.w};

    float out[4];
    #pragma unroll
    for (int j = 0; j < 4; j++) {
        float c   = cc[j + 1];
        float dx  = 0.5f  * (cc[j + 2] - cc[j]);
        float dy  = 0.5f  * (dd[j + 1] - uu[j + 1]);
        float dxx = cc[j + 2] + cc[j] - 2.f * c;
        float dyy = dd[j + 1] + uu[j + 1] - 2.f * c;
        float dxy = 0.25f * ((dd[j + 2] - uu[j + 2]) - (dd[j] - uu[j]));
        out[j] = f0a[j] * c + f1a[j] * dx + f2a[j] * dy
               - (f3a[j] * dxx + f6a[j] * dyy + f4a[j] * dxy);
    }
    return make_float4(out[0], out[1], out[2], out[3]);
}

// Kernel 2: v = A(x)   -- 256 threads, 4 rows x 64 float4-lanes per block
__global__ __launch_bounds__(256) void stencil1_kernel(const float* __restrict__ x)
{
    const int tx = threadIdx.x & 63;
    const int ty = threadIdx.x >> 6;
    const int h  = blockIdx.x * 4 + ty;
    const int t  = blockIdx.y;
    const int b  = blockIdx.z;
    const int base = ((b * Tn + t) * Hn) * Wn;
    const int w4 = tx * 4;
    float4 r = applyA4(x, base, h, w4);
    *(float4*)&g_v[base + h * Wn + w4] = r;
}

// Kernel 3: r = x + A(v) - x_prev ; accumulate sum(D r^2)
__global__ __launch_bounds__(256) void stencil2_kernel(const float* __restrict__ x)
{
    const int tx = threadIdx.x & 63;
    const int ty = threadIdx.x >> 6;
    const int h  = blockIdx.x * 4 + ty;
    const int t  = blockIdx.y;
    const int b  = blockIdx.z;
    const int base = ((b * Tn + t) * Hn) * Wn;
    const int w4 = tx * 4;
    const int p  = base + h * Wn + w4;

    float4 Av = applyA4(g_v, base, h, w4);
    float4 xv = *(const float4*)&x[p];
    float4 xp = make_float4(0.f, 0.f, 0.f, 0.f);
    if (t > 0) xp = *(const float4*)&x[p - Hn * Wn];
    float4 f7 = *(const float4*)&g_fields[7][p];

    float r0 = xv.x + Av.x - xp.x;
    float r1 = xv.y + Av.y - xp.y;
    float r2 = xv.z + Av.z - xp.z;
    float r3 = xv.w + Av.w - xp.w;
    float val = f7.x * r0 * r0 + f7.y * r1 * r1 + f7.z * r2 * r2 + f7.w * r3 * r3;

    #pragma unroll
    for (int off = 16; off; off >>= 1)
        val += __shfl_down_sync(0xffffffffu, val, off);

    __shared__ float red[8];
    const int lane = threadIdx.x & 31;
    const int wid  = threadIdx.x >> 5;
    if (lane == 0) red[wid] = val;
    __syncthreads();
    if (wid == 0) {
        float s = (lane < 8) ? red[lane] : 0.f;
        #pragma unroll
        for (int off = 4; off; off >>= 1)
            s += __shfl_down_sync(0xffffffffu, s, off);
        if (lane == 0) atomicAdd(&g_acc[0], (double)s);
    }
}

__global__ void finalize_kernel(float* __restrict__ out)
{
    out[0] = (float)(0.5 * (g_acc[0] - g_acc[1]));
}

// ---------------------------------------------------------------------------
extern "C" void kernel_launch(void* const* d_in, const int* in_sizes, int n_in,
                              void* d_out, int out_size)
{
    const float* x  = (const float*)d_in[0];
    const float* cw = (const float*)d_in[1];
    float* out = (float*)d_out;

    init_acc_kernel<<<1, 1>>>();
    transpose_w_kernel<<<18, 256>>>(cw);

    dim3 gA(Wn / TW, Hn / TH, Bn);       // 8 x 64 x 4 = 2048 blocks
    conv_kernel<<<gA, 256>>>(x);

    dim3 gS(Hn / 4, Tn, Bn);             // 64 x 8 x 4 = 2048 blocks, 256 thr
    stencil1_kernel<<<gS, 256>>>(x);
    stencil2_kernel<<<gS, 256>>>(x);

    finalize_kernel<<<1, 1>>>(out);
}